// round 4
// baseline (speedup 1.0000x reference)
#include <cuda_runtime.h>

// GyroLoss forward, single fused kernel.
// One thread per 8-increment half-group (262144 threads). Binary-tree
// composition in-thread (matches reference association), lane-pair shuffle for
// the 16-group, lane-quad shuffle for the level-5 pair. Converged huber/log
// epilogue with per-lane operand selection. Last-block finalize.

#define DT_F 0.01f
#define HUBER_F 0.005f
#define NPER4 2048   // groups per batch at level 4
#define NPER5 1024   // pairs per batch at level 5
#define N0 5
#define TPB 256

__device__ double g_sum4 = 0.0;
__device__ double g_sum5 = 0.0;
__device__ unsigned int g_count = 0u;

// Full-accuracy exp (used for xs; angle can be O(1..6))
__device__ __forceinline__ void so3_exp9_full(float x, float y, float z, float R[9]) {
    float sq = x * x + y * y + z * z;
    float s, c;
    if (sq < 1e-12f) {
        s = 1.0f - sq * (1.0f / 6.0f);
        c = 0.5f - sq * (1.0f / 24.0f);
    } else {
        float a = sqrtf(fmaxf(sq, 1e-16f));
        float sa, ca;
        sincosf(a, &sa, &ca);
        s = sa / a;
        c = (1.0f - ca) / (a * a);
    }
    float xx = x * x, yy = y * y, zz = z * z;
    float xy = x * y, xz = x * z, yz = y * z;
    R[0] = 1.0f - c * (yy + zz);
    R[1] = c * xy - s * z;
    R[2] = c * xz + s * y;
    R[3] = c * xy + s * z;
    R[4] = 1.0f - c * (xx + zz);
    R[5] = c * yz - s * x;
    R[6] = c * xz - s * y;
    R[7] = c * yz + s * x;
    R[8] = 1.0f - c * (xx + yy);
}

// Small-angle exp: |phi| = dt*|w|, sq <= ~1e-2. Taylor error < 2e-10.
__device__ __forceinline__ void so3_exp9_small(float x, float y, float z, float R[9]) {
    float sq = x * x + y * y + z * z;
    float s = 1.0f + sq * (-(1.0f / 6.0f) + sq * (1.0f / 120.0f));
    float c = 0.5f + sq * (-(1.0f / 24.0f) + sq * (1.0f / 720.0f));
    float xx = x * x, yy = y * y, zz = z * z;
    float xy = x * y, xz = x * z, yz = y * z;
    R[0] = 1.0f - c * (yy + zz);
    R[1] = c * xy - s * z;
    R[2] = c * xz + s * y;
    R[3] = c * xy + s * z;
    R[4] = 1.0f - c * (xx + zz);
    R[5] = c * yz - s * x;
    R[6] = c * xz - s * y;
    R[7] = c * yz + s * x;
    R[8] = 1.0f - c * (xx + yy);
}

__device__ __forceinline__ void mm3(const float A[9], const float B[9], float C[9]) {
#pragma unroll
    for (int i = 0; i < 3; i++) {
#pragma unroll
        for (int j = 0; j < 3; j++) {
            C[3 * i + j] = fmaf(A[3 * i + 0], B[0 + j],
                           fmaf(A[3 * i + 1], B[3 + j],
                                A[3 * i + 2] * B[6 + j]));
        }
    }
}

// sum of Huber losses of so3_log(A^T B) / HUBER over 3 components
__device__ __forceinline__ float huber3_bmtm_log(const float A[9], const float B[9]) {
    float m00 = A[0]*B[0] + A[3]*B[3] + A[6]*B[6];
    float m11 = A[1]*B[1] + A[4]*B[4] + A[7]*B[7];
    float m22 = A[2]*B[2] + A[5]*B[5] + A[8]*B[8];
    float m21 = A[2]*B[1] + A[5]*B[4] + A[8]*B[7];
    float m12 = A[1]*B[2] + A[4]*B[5] + A[7]*B[8];
    float m02 = A[0]*B[2] + A[3]*B[5] + A[6]*B[8];
    float m20 = A[2]*B[0] + A[5]*B[3] + A[8]*B[6];
    float m10 = A[1]*B[0] + A[4]*B[3] + A[7]*B[6];
    float m01 = A[0]*B[1] + A[3]*B[4] + A[6]*B[7];
    float tr  = m00 + m11 + m22;
    float cs  = fminf(fmaxf(0.5f * (tr - 1.0f), -1.0f + 1e-7f), 1.0f - 1e-7f);
    float ang = acosf(cs);
    float sfac = ang / (2.0f * sinf(ang));
    float v0 = sfac * (m21 - m12);
    float v1 = sfac * (m02 - m20);
    float v2 = sfac * (m10 - m01);
    float acc = 0.0f;
#pragma unroll
    for (int t = 0; t < 3; t++) {
        float z = ((t == 0) ? v0 : (t == 1) ? v1 : v2) * (1.0f / HUBER_F);
        float az = fabsf(z);
        acc += (az < 1.0f) ? (0.5f * z * z) : (az - 0.5f);
    }
    return acc;
}

__global__ void __launch_bounds__(TPB)
gyro_main_kernel(const float* __restrict__ xs, const float* __restrict__ hx,
                 float* __restrict__ out, int cnt4, int cnt5) {
    int t = blockIdx.x * blockDim.x + threadIdx.x;   // half-group index (8 incr)

    // --- load 8 increments (24 floats, coalesced float4) ---
    const float4* hp = reinterpret_cast<const float4*>(hx) + (size_t)t * 6;
    float v[24];
    {
        float4 q0 = hp[0], q1 = hp[1], q2 = hp[2], q3 = hp[3], q4 = hp[4], q5 = hp[5];
        v[0]=q0.x; v[1]=q0.y; v[2]=q0.z; v[3]=q0.w; v[4]=q1.x; v[5]=q1.y;
        v[6]=q1.z; v[7]=q1.w; v[8]=q2.x; v[9]=q2.y; v[10]=q2.z; v[11]=q2.w;
        v[12]=q3.x; v[13]=q3.y; v[14]=q3.z; v[15]=q3.w; v[16]=q4.x; v[17]=q4.y;
        v[18]=q4.z; v[19]=q4.w; v[20]=q5.x; v[21]=q5.y; v[22]=q5.z; v[23]=q5.w;
    }

    // --- binary-tree compose 8 exps (matches reference association) ---
    float O8[9];
    {
        float P0[9], P1[9], Q0[9], Q1[9];
        {
            float Ra[9], Rb[9];
            so3_exp9_small(DT_F*v[0],  DT_F*v[1],  DT_F*v[2],  Ra);
            so3_exp9_small(DT_F*v[3],  DT_F*v[4],  DT_F*v[5],  Rb);
            mm3(Ra, Rb, P0);
            so3_exp9_small(DT_F*v[6],  DT_F*v[7],  DT_F*v[8],  Ra);
            so3_exp9_small(DT_F*v[9],  DT_F*v[10], DT_F*v[11], Rb);
            mm3(Ra, Rb, P1);
            so3_exp9_small(DT_F*v[12], DT_F*v[13], DT_F*v[14], Ra);
            so3_exp9_small(DT_F*v[15], DT_F*v[16], DT_F*v[17], Rb);
            mm3(Ra, Rb, Q0);
            so3_exp9_small(DT_F*v[18], DT_F*v[19], DT_F*v[20], Ra);
            so3_exp9_small(DT_F*v[21], DT_F*v[22], DT_F*v[23], Rb);
            mm3(Ra, Rb, Q1);
        }
        float U[9], W[9];
        mm3(P0, P1, U);
        mm3(Q0, Q1, W);
        mm3(U, W, O8);
    }

    // --- 16-group: even lane owns group g = t>>1; pull partner O8 ---
    float O16[9];
    {
        float Op[9];
#pragma unroll
        for (int k = 0; k < 9; k++)
            Op[k] = __shfl_down_sync(0xFFFFFFFFu, O8[k], 1);
        mm3(O8, Op, O16);            // valid on even lanes
    }

    // --- ground-truth rotation: both lanes of a pair load same float4 (bcast) ---
    float R16[9];
    {
        float4 qa = *reinterpret_cast<const float4*>(xs + (size_t)(t >> 1) * 48);
        so3_exp9_full(qa.x, qa.y, qa.z, R16);   // identical/valid on both lanes
    }

    // --- level-5 operands: lane ≡2 (mod 4) combines groups 2j, 2j+1 ---
    float O32[9], R32[9];
    {
        float Opv[9], Rpv[9];
#pragma unroll
        for (int k = 0; k < 9; k++) {
            Opv[k] = __shfl_up_sync(0xFFFFFFFFu, O16[k], 2);
            Rpv[k] = __shfl_up_sync(0xFFFFFFFFu, R16[k], 2);
        }
        mm3(Opv, O16, O32);          // valid on lanes ≡2 (mod 4)
        mm3(Rpv, R16, R32);
    }
    // route level-5 operands to lane ≡3 so lanes ≡0,≡2 keep level-4 work
    float O32s[9], R32s[9];
#pragma unroll
    for (int k = 0; k < 9; k++) {
        O32s[k] = __shfl_up_sync(0xFFFFFFFFu, O32[k], 1);
        R32s[k] = __shfl_up_sync(0xFFFFFFFFu, R32[k], 1);
    }

    // --- converged huber/log with per-lane operand select ---
    int m = t & 3;
    float A[9], B[9];
#pragma unroll
    for (int k = 0; k < 9; k++) {
        A[k] = (m == 3) ? O32s[k] : O16[k];
        B[k] = (m == 3) ? R32s[k] : R16[k];
    }
    float h = huber3_bmtm_log(A, B);

    float s4 = 0.0f, s5 = 0.0f;
    if ((m & 1) == 0) {                       // lanes ≡0,2: level-4, group g=t>>1
        int i4 = (t >> 1) & (NPER4 - 1);
        if (i4 >= N0) s4 = h;
    } else if (m == 3) {                      // lane ≡3: level-5, pair p=t>>2
        int j5 = (t >> 2) & (NPER5 - 1);
        if (j5 >= N0) s5 = h;
    }

    // --- reduction ---
#pragma unroll
    for (int off = 16; off > 0; off >>= 1) {
        s4 += __shfl_down_sync(0xFFFFFFFFu, s4, off);
        s5 += __shfl_down_sync(0xFFFFFFFFu, s5, off);
    }
    __shared__ float sh4[TPB / 32];
    __shared__ float sh5[TPB / 32];
    int lane = threadIdx.x & 31;
    int warp = threadIdx.x >> 5;
    if (lane == 0) { sh4[warp] = s4; sh5[warp] = s5; }
    __syncthreads();

    if (threadIdx.x == 0) {
        float b4 = 0.0f, b5 = 0.0f;
#pragma unroll
        for (int w = 0; w < TPB / 32; w++) { b4 += sh4[w]; b5 += sh5[w]; }
        atomicAdd(&g_sum4, (double)b4);
        atomicAdd(&g_sum5, (double)b5);
        __threadfence();
        unsigned int ticket = atomicAdd(&g_count, 1u);
        if (ticket == gridDim.x - 1) {
            double s4t = atomicAdd(&g_sum4, 0.0);
            double s5t = atomicAdd(&g_sum5, 0.0);
            // loss = W*HUBER^2 * (mean4 + 0.5*mean5); W*HUBER^2 = 25
            double loss = 25.0 * (s4t / (double)cnt4 + 0.5 * s5t / (double)cnt5);
            out[0] = (float)loss;
            g_sum4 = 0.0;
            g_sum5 = 0.0;
            __threadfence();
            g_count = 0u;
        }
    }
}

extern "C" void kernel_launch(void* const* d_in, const int* in_sizes, int n_in,
                              void* d_out, int out_size) {
    const float* xs = (const float*)d_in[0];
    // d_in[1] = dp, unused by forward
    const float* hx = (const float*)d_in[2];

    int total = in_sizes[2];              // N*T*3 = 6291456
    int halves = total / 24;              // 262144 threads (8 increments each)
    int groups = total / 48;              // 131072
    int nbatch = 64;                      // N
    int g4_per_batch = groups / nbatch;   // 2048
    int g5_per_batch = g4_per_batch / 2;  // 1024
    int cnt4 = nbatch * (g4_per_batch - N0) * 3;   // 392256
    int cnt5 = nbatch * (g5_per_batch - N0) * 3;   // 195648

    gyro_main_kernel<<<halves / TPB, TPB>>>(xs, hx, (float*)d_out, cnt4, cnt5);
}

// round 5
// speedup vs baseline: 1.1800x; 1.1800x over previous
#include <cuda_runtime.h>

// GyroLoss forward, single fused kernel — quaternion formulation.
// One thread per 8-increment half-group (262144 threads). Binary-tree quat
// composition (matches reference association), lane shuffles for the 16-group
// and level-5 combines, converged log/huber epilogue. Last-block finalize.

#define DT_F 0.01f
#define HUBER_F 0.005f
#define NPER4 2048
#define NPER5 1024
#define N0 5
#define TPB 256

__device__ double g_sum4 = 0.0;
__device__ double g_sum5 = 0.0;
__device__ unsigned int g_count = 0u;

// Hamilton product c = a ⊗ b  (R(a⊗b) = R(a)·R(b)); w at index 0.
__device__ __forceinline__ void qmul(const float a[4], const float b[4], float c[4]) {
    c[0] = a[0]*b[0] - a[1]*b[1] - a[2]*b[2] - a[3]*b[3];
    c[1] = a[0]*b[1] + a[1]*b[0] + a[2]*b[3] - a[3]*b[2];
    c[2] = a[0]*b[2] - a[1]*b[3] + a[2]*b[0] + a[3]*b[1];
    c[3] = a[0]*b[3] + a[1]*b[2] - a[2]*b[1] + a[3]*b[0];
}

// c = conj(a) ⊗ b   (relative rotation A^T B)
__device__ __forceinline__ void qcmul(const float a[4], const float b[4], float c[4]) {
    c[0] = a[0]*b[0] + a[1]*b[1] + a[2]*b[2] + a[3]*b[3];
    c[1] = a[0]*b[1] - a[1]*b[0] - a[2]*b[3] + a[3]*b[2];
    c[2] = a[0]*b[2] + a[1]*b[3] - a[2]*b[0] - a[3]*b[1];
    c[3] = a[0]*b[3] - a[1]*b[2] + a[2]*b[1] - a[3]*b[0];
}

// exp of small phi = dt*(x,y,z) -> quaternion. sq = |phi|^2 <= ~2e-3.
// w = cos(h), v = (sin(h)/h)*phi/2, h = |phi|/2; Taylor error < 1e-12.
__device__ __forceinline__ void qexp_small(float x, float y, float z, float q[4]) {
    float rs = x*x + y*y + z*z;                 // raw |w|^2
    float hq = (0.25f * DT_F * DT_F) * rs;      // (|phi|/2)^2
    q[0] = 1.0f + hq * (-0.5f + hq * (1.0f / 24.0f));
    float sf = (0.5f * DT_F) * (1.0f + hq * (-(1.0f / 6.0f) + hq * (1.0f / 120.0f)));
    q[1] = sf * x; q[2] = sf * y; q[3] = sf * z;
}

// full-range exp (xs path): angle up to ~6
__device__ __forceinline__ void qexp_full(float x, float y, float z, float q[4]) {
    float sq = x*x + y*y + z*z;
    float a = sqrtf(fmaxf(sq, 1e-16f));
    float sa, ca;
    sincosf(0.5f * a, &sa, &ca);
    float sf = sa / a;          // a >= 1e-8: sin(a/2)/a -> 0.5 smoothly
    q[0] = ca; q[1] = sf * x; q[2] = sf * y; q[3] = sf * z;
}

// sum of Huber(phi_i / HUBER) where phi = so3_log of the rotation of quat q.
// Equivalent to reference matrix log: tr = 4w^2-1 -> angle = 2 acos(|w|),
// vee = 4wv -> phi = (2 atan2(|v|, |w|)/|v|) * v (sign-folded).
__device__ __forceinline__ float huber3_qlog(const float q[4]) {
    float w = q[0], x = q[1], y = q[2], z = q[3];
    float sgn = (w < 0.0f) ? -1.0f : 1.0f;
    w *= sgn; x *= sgn; y *= sgn; z *= sgn;
    float nv = sqrtf(x*x + y*y + z*z);
    float th = 2.0f * atan2f(nv, w);
    float f = th / fmaxf(nv, 1e-20f) * (1.0f / HUBER_F);
    float acc = 0.0f;
#pragma unroll
    for (int t = 0; t < 3; t++) {
        float zz = f * ((t == 0) ? x : (t == 1) ? y : z);
        float az = fabsf(zz);
        acc += (az < 1.0f) ? (0.5f * zz * zz) : (az - 0.5f);
    }
    return acc;
}

__global__ void __launch_bounds__(TPB)
gyro_main_kernel(const float* __restrict__ xs, const float* __restrict__ hx,
                 float* __restrict__ out, int cnt4, int cnt5) {
    int t = blockIdx.x * blockDim.x + threadIdx.x;   // half-group (8 increments)
    int lane = threadIdx.x & 31;

    // --- load 8 increments (24 floats = 6 float4, coalesced) ---
    const float4* hp = reinterpret_cast<const float4*>(hx) + (size_t)t * 6;
    float4 f0 = hp[0], f1 = hp[1], f2 = hp[2], f3 = hp[3], f4 = hp[4], f5 = hp[5];
    float v[24] = {f0.x,f0.y,f0.z,f0.w, f1.x,f1.y,f1.z,f1.w, f2.x,f2.y,f2.z,f2.w,
                   f3.x,f3.y,f3.z,f3.w, f4.x,f4.y,f4.z,f4.w, f5.x,f5.y,f5.z,f5.w};

    // --- binary tree: 8 leaves -> q8 (matches reference association) ---
    float p0[4], p1[4], p2[4], p3[4];
    {
        float la[4], lb[4];
        qexp_small(v[0],  v[1],  v[2],  la);
        qexp_small(v[3],  v[4],  v[5],  lb);
        qmul(la, lb, p0);
        qexp_small(v[6],  v[7],  v[8],  la);
        qexp_small(v[9],  v[10], v[11], lb);
        qmul(la, lb, p1);
        qexp_small(v[12], v[13], v[14], la);
        qexp_small(v[15], v[16], v[17], lb);
        qmul(la, lb, p2);
        qexp_small(v[18], v[19], v[20], la);
        qexp_small(v[21], v[22], v[23], lb);
        qmul(la, lb, p3);
    }
    float u0[4], u1[4], q8[4];
    qmul(p0, p1, u0);
    qmul(p2, p3, u1);
    qmul(u0, u1, q8);

    // --- 16-group: even lane combines with odd partner ---
    float q16[4];
    {
        float qp[4];
#pragma unroll
        for (int k = 0; k < 4; k++)
            qp[k] = __shfl_down_sync(0xFFFFFFFFu, q8[k], 1);
        qmul(q8, qp, q16);                       // valid on even lanes
    }

    // --- ground-truth quat for own group (pair broadcasts same float4) ---
    float qR[4];
    {
        float4 qa = *reinterpret_cast<const float4*>(xs + (size_t)(t >> 1) * 48);
        qexp_full(qa.x, qa.y, qa.z, qR);          // valid on all lanes
    }

    // --- level-5 on lane ≡3 (mod 4): gather group quats from lanes lb, lb+2 ---
    int lb = lane & ~3;
    float q32[4], qR32[4];
    {
        float qa[4], qb[4], ra[4];
#pragma unroll
        for (int k = 0; k < 4; k++) {
            qa[k] = __shfl_sync(0xFFFFFFFFu, q16[k], lb);
            qb[k] = __shfl_sync(0xFFFFFFFFu, q16[k], lb | 2);
            ra[k] = __shfl_sync(0xFFFFFFFFu, qR[k],  lb);
        }
        qmul(qa, qb, q32);                        // used on lane ≡3
        qmul(ra, qR, qR32);                       // lane3's own qR is group 2j+1
    }

    // --- converged relative-rotation log + huber ---
    int m = t & 3;
    float relA[4], relB[4], rel[4];
    qcmul(q16, qR, relA);                         // level-4 (valid even lanes)
    qcmul(q32, qR32, relB);                       // level-5 (valid lane ≡3)
#pragma unroll
    for (int k = 0; k < 4; k++) rel[k] = (m == 3) ? relB[k] : relA[k];
    float h = huber3_qlog(rel);

    float s4 = 0.0f, s5 = 0.0f;
    if ((m & 1) == 0) {                           // lanes ≡0,2: level-4
        int i4 = (t >> 1) & (NPER4 - 1);
        if (i4 >= N0) s4 = h;
    } else if (m == 3) {                          // lane ≡3: level-5
        int j5 = (t >> 2) & (NPER5 - 1);
        if (j5 >= N0) s5 = h;
    }

    // --- reduction ---
#pragma unroll
    for (int off = 16; off > 0; off >>= 1) {
        s4 += __shfl_down_sync(0xFFFFFFFFu, s4, off);
        s5 += __shfl_down_sync(0xFFFFFFFFu, s5, off);
    }
    __shared__ float sh4[TPB / 32];
    __shared__ float sh5[TPB / 32];
    int warp = threadIdx.x >> 5;
    if (lane == 0) { sh4[warp] = s4; sh5[warp] = s5; }
    __syncthreads();

    if (threadIdx.x == 0) {
        float b4 = 0.0f, b5 = 0.0f;
#pragma unroll
        for (int w = 0; w < TPB / 32; w++) { b4 += sh4[w]; b5 += sh5[w]; }
        atomicAdd(&g_sum4, (double)b4);
        atomicAdd(&g_sum5, (double)b5);
        __threadfence();
        unsigned int ticket = atomicAdd(&g_count, 1u);
        if (ticket == gridDim.x - 1) {
            double s4t = atomicAdd(&g_sum4, 0.0);
            double s5t = atomicAdd(&g_sum5, 0.0);
            // loss = W*HUBER^2 * (mean4 + 0.5*mean5); W*HUBER^2 = 25
            double loss = 25.0 * (s4t / (double)cnt4 + 0.5 * s5t / (double)cnt5);
            out[0] = (float)loss;
            g_sum4 = 0.0;
            g_sum5 = 0.0;
            __threadfence();
            g_count = 0u;
        }
    }
}

extern "C" void kernel_launch(void* const* d_in, const int* in_sizes, int n_in,
                              void* d_out, int out_size) {
    const float* xs = (const float*)d_in[0];
    // d_in[1] = dp, unused by forward
    const float* hx = (const float*)d_in[2];

    int total = in_sizes[2];              // N*T*3 = 6291456
    int halves = total / 24;              // 262144 threads (8 increments each)
    int groups = total / 48;              // 131072
    int nbatch = 64;
    int g4_per_batch = groups / nbatch;   // 2048
    int g5_per_batch = g4_per_batch / 2;  // 1024
    int cnt4 = nbatch * (g4_per_batch - N0) * 3;   // 392256
    int cnt5 = nbatch * (g5_per_batch - N0) * 3;   // 195648

    gyro_main_kernel<<<halves / TPB, TPB>>>(xs, hx, (float*)d_out, cnt4, cnt5);
}